// round 3
// baseline (speedup 1.0000x reference)
#include <cuda_runtime.h>

// ---------------------------------------------------------------------------
// DummyGCN4: 4-layer GCN, output = h3[node 1] only.
// R3: single persistent kernel (148 blocks x 1024 threads, one resident
// wave) with software grid barriers. Backward-slices the dependence cone of
// node 1, captures matching edge lists during the backward scans, then runs
// the tiny forward computation. dst/src stay L2-resident across phases.
// ---------------------------------------------------------------------------

#define NBLK 148
#define NTHR 1024
#define MAXN 50048
#define BMW  1568
#define OUT_NODE 1
#define E1CAP  16384      // edges with dst == OUT_NODE
#define E2CAP  65536      // edges with dst in B2
#define EBCAP  262144     // edges with dst in B1

__device__ unsigned g_B0[BMW], g_B1[BMW], g_B2[BMW];
__device__ int   g_list0[MAXN], g_list1[MAXN], g_list2[MAXN];
__device__ int   g_cnt0, g_cnt1, g_cnt2;
__device__ int   g_e1s[E1CAP];                 __device__ int g_e1n;
__device__ int   g_e2s[E2CAP],  g_e2d[E2CAP];  __device__ int g_e2n;
__device__ int   g_ebs[EBCAP],  g_ebd[EBCAP];  __device__ int g_ebn;
__device__ float g_agg0[MAXN];
__device__ float g_agg1[(size_t)MAXN * 64];
__device__ float g_x2[(size_t)MAXN * 64];
__device__ float g_agg2[(size_t)MAXN * 64];
__device__ float g_x3[MAXN];

// grid barrier state (count is reset by each release; gen monotonic)
__device__ unsigned g_bar_count;
__device__ unsigned g_bar_gen;

__device__ __forceinline__ float lrelu(float x) { return x >= 0.f ? x : 0.01f * x; }
__device__ __forceinline__ bool tb(const unsigned* b, int i) {
    return (__ldcg(&b[i >> 5]) >> (i & 31)) & 1u;
}
__device__ __forceinline__ void zero64(float* a) {
    float4 z = make_float4(0.f, 0.f, 0.f, 0.f);
    float4* a4 = (float4*)a;
    #pragma unroll
    for (int j = 0; j < 16; j++) a4[j] = z;
}

__device__ __forceinline__ void grid_barrier() {
    __syncthreads();
    if (threadIdx.x == 0) {
        unsigned gen = *(volatile unsigned*)&g_bar_gen;
        __threadfence();
        unsigned arrived = atomicAdd(&g_bar_count, 1u);
        if (arrived == (unsigned)(gridDim.x - 1)) {
            g_bar_count = 0u;
            __threadfence();
            atomicAdd(&g_bar_gen, 1u);
        } else {
            while (*(volatile unsigned*)&g_bar_gen == gen) __nanosleep(32);
        }
        __threadfence();
    }
    __syncthreads();
}

// ---- scan hit handlers --------------------------------------------------
__device__ __forceinline__ void hit32(const int* __restrict__ src, int e) {
    int s = __ldg(&src[e]);
    int p = atomicAdd(&g_e1n, 1);
    if (p < E1CAP) g_e1s[p] = s;
    unsigned m = 1u << (s & 31);
    unsigned old = atomicOr(&g_B2[s >> 5], m);
    if (!(old & m)) {
        int q = atomicAdd(&g_cnt2, 1);
        g_list2[q] = s;
        zero64(&g_agg2[(size_t)s * 64]);
    }
}
__device__ __forceinline__ void hit21(const int* __restrict__ src, int e, int d) {
    int s = __ldg(&src[e]);
    int p = atomicAdd(&g_e2n, 1);
    if (p < E2CAP) { g_e2s[p] = s; g_e2d[p] = d; }
    unsigned m = 1u << (s & 31);
    unsigned old = atomicOr(&g_B1[s >> 5], m);
    if (!(old & m)) {
        int q = atomicAdd(&g_cnt1, 1);
        g_list1[q] = s;
        zero64(&g_agg1[(size_t)s * 64]);
    }
}
__device__ __forceinline__ void hit10(const int* __restrict__ src, int e, int d) {
    int s = __ldg(&src[e]);
    int p = atomicAdd(&g_ebn, 1);
    if (p < EBCAP) { g_ebs[p] = s; g_ebd[p] = d; }
    unsigned m = 1u << (s & 31);
    unsigned old = atomicOr(&g_B0[s >> 5], m);
    if (!(old & m)) {
        int q = atomicAdd(&g_cnt0, 1);
        g_list0[q] = s;
        g_agg0[s] = 0.f;
    }
}

// ---------------------------------------------------------------------------
__global__ void __launch_bounds__(NTHR, 1)
gcn_persistent(const float* __restrict__ in_feat,
               const int* __restrict__ src, const int* __restrict__ dst, int E,
               const float* __restrict__ W0, const float* __restrict__ b0,
               const float* __restrict__ W1, const float* __restrict__ b1,
               const float* __restrict__ W2, const float* __restrict__ b2,
               const float* __restrict__ W3, const float* __restrict__ b3,
               float* __restrict__ out) {
    const int tid  = blockIdx.x * NTHR + threadIdx.x;
    const int NT   = gridDim.x * NTHR;
    const int lane = threadIdx.x & 31;
    const int gw   = tid >> 5;
    const int NW   = NT >> 5;
    const int C4   = E >> 2;            // full int4 chunks
    const int tail = C4 << 2;

    // ---- phase 0: clear ----
    for (int i = tid; i < BMW; i += NT) { g_B0[i] = 0; g_B1[i] = 0; g_B2[i] = 0; }
    if (tid == 0) { g_cnt0 = 0; g_cnt1 = 0; g_cnt2 = 0; g_e1n = 0; g_e2n = 0; g_ebn = 0; }
    grid_barrier();

    // ---- phase 1: scan dst == OUT_NODE -> B2, list2, e1 ----
    for (int c = tid; c < C4; c += NT) {
        int4 d4 = __ldg((const int4*)dst + c);
        int base = c << 2;
        if (d4.x == OUT_NODE) hit32(src, base + 0);
        if (d4.y == OUT_NODE) hit32(src, base + 1);
        if (d4.z == OUT_NODE) hit32(src, base + 2);
        if (d4.w == OUT_NODE) hit32(src, base + 3);
    }
    for (int e = tail + tid; e < E; e += NT) if (__ldg(&dst[e]) == OUT_NODE) hit32(src, e);
    grid_barrier();

    // ---- phase 2: scan dst in B2 -> B1, list1, e2 ----
    for (int c = tid; c < C4; c += NT) {
        int4 d4 = __ldg((const int4*)dst + c);
        int base = c << 2;
        if (tb(g_B2, d4.x)) hit21(src, base + 0, d4.x);
        if (tb(g_B2, d4.y)) hit21(src, base + 1, d4.y);
        if (tb(g_B2, d4.z)) hit21(src, base + 2, d4.z);
        if (tb(g_B2, d4.w)) hit21(src, base + 3, d4.w);
    }
    for (int e = tail + tid; e < E; e += NT) { int d = __ldg(&dst[e]); if (tb(g_B2, d)) hit21(src, e, d); }
    grid_barrier();

    // ---- phase 3: scan dst in B1 -> B0, list0, eb ----
    for (int c = tid; c < C4; c += NT) {
        int4 d4 = __ldg((const int4*)dst + c);
        int base = c << 2;
        if (tb(g_B1, d4.x)) hit10(src, base + 0, d4.x);
        if (tb(g_B1, d4.y)) hit10(src, base + 1, d4.y);
        if (tb(g_B1, d4.z)) hit10(src, base + 2, d4.z);
        if (tb(g_B1, d4.w)) hit10(src, base + 3, d4.w);
    }
    for (int e = tail + tid; e < E; e += NT) { int d = __ldg(&dst[e]); if (tb(g_B1, d)) hit10(src, e, d); }
    grid_barrier();

    // ---- phase 4: layer-0 aggregation: agg0[d] += in_feat[src], dst in B0 ----
    for (int c = tid; c < C4; c += NT) {
        int4 d4 = __ldg((const int4*)dst + c);
        int base = c << 2;
        if (tb(g_B0, d4.x)) atomicAdd(&g_agg0[d4.x], __ldg(&in_feat[__ldg(&src[base + 0])]));
        if (tb(g_B0, d4.y)) atomicAdd(&g_agg0[d4.y], __ldg(&in_feat[__ldg(&src[base + 1])]));
        if (tb(g_B0, d4.z)) atomicAdd(&g_agg0[d4.z], __ldg(&in_feat[__ldg(&src[base + 2])]));
        if (tb(g_B0, d4.w)) atomicAdd(&g_agg0[d4.w], __ldg(&in_feat[__ldg(&src[base + 3])]));
    }
    for (int e = tail + tid; e < E; e += NT) {
        int d = __ldg(&dst[e]);
        if (tb(g_B0, d)) atomicAdd(&g_agg0[d], __ldg(&in_feat[__ldg(&src[e])]));
    }
    grid_barrier();

    // ---- phase 5: agg1[d][:] += lrelu(agg0[s]*W0 + b0)  (h0 fused, warp/edge) ----
    {
        int n = min(g_ebn, EBCAP);
        float w0a = __ldg(&W0[lane]),      w0b = __ldg(&W0[lane + 32]);
        float b0a = __ldg(&b0[lane]),      b0b = __ldg(&b0[lane + 32]);
        for (int i = gw; i < n; i += NW) {
            int s = g_ebs[i], d = g_ebd[i];
            float a0 = __ldcg(&g_agg0[s]);
            float ha = lrelu(fmaf(a0, w0a, b0a));
            float hb = lrelu(fmaf(a0, w0b, b0b));
            float* a = &g_agg1[(size_t)d * 64];
            atomicAdd(&a[lane],      ha);
            atomicAdd(&a[lane + 32], hb);
        }
    }
    grid_barrier();

    // ---- phase 6: per node v in list1: h1 = lrelu(agg1@W1+b1); x2 = h1@W2 ----
    {
        int n = g_cnt1;
        for (int i = gw; i < n; i += NW) {
            int v = g_list1[i];
            float a0 = __ldcg(&g_agg1[(size_t)v * 64 + lane]);
            float a1 = __ldcg(&g_agg1[(size_t)v * 64 + lane + 32]);
            // h1 cols: lane, lane+32, lane+64, lane+96
            float h0r = __ldg(&b1[lane]);
            float h1r = __ldg(&b1[lane + 32]);
            float h2r = __ldg(&b1[lane + 64]);
            float h3r = __ldg(&b1[lane + 96]);
            #pragma unroll
            for (int k = 0; k < 64; k++) {
                float ak = __shfl_sync(0xffffffffu, (k < 32) ? a0 : a1, k & 31);
                const float* wr = &W1[k * 128];
                h0r = fmaf(ak, __ldg(&wr[lane]),      h0r);
                h1r = fmaf(ak, __ldg(&wr[lane + 32]), h1r);
                h2r = fmaf(ak, __ldg(&wr[lane + 64]), h2r);
                h3r = fmaf(ak, __ldg(&wr[lane + 96]), h3r);
            }
            float h[4] = { lrelu(h0r), lrelu(h1r), lrelu(h2r), lrelu(h3r) };
            // x2 cols: lane, lane+32
            float x0 = 0.f, x1 = 0.f;
            #pragma unroll
            for (int k = 0; k < 128; k++) {
                float hk = __shfl_sync(0xffffffffu, h[k >> 5], k & 31);
                const float* wr = &W2[k * 64];
                x0 = fmaf(hk, __ldg(&wr[lane]),      x0);
                x1 = fmaf(hk, __ldg(&wr[lane + 32]), x1);
            }
            g_x2[(size_t)v * 64 + lane]      = x0;
            g_x2[(size_t)v * 64 + lane + 32] = x1;
        }
    }
    grid_barrier();

    // ---- phase 7 (block 0 only): agg2, h2+x3, final reduce, output ----
    if (blockIdx.x != 0) return;
    {
        int n2 = min(g_e2n, E2CAP);
        int bw = threadIdx.x >> 5;          // 0..31
        for (int i = bw; i < n2; i += 32) {
            int s = g_e2s[i], d = g_e2d[i];
            float xa = __ldcg(&g_x2[(size_t)s * 64 + lane]);
            float xb = __ldcg(&g_x2[(size_t)s * 64 + lane + 32]);
            float* a = &g_agg2[(size_t)d * 64];
            atomicAdd(&a[lane],      xa);
            atomicAdd(&a[lane + 32], xb);
        }
        __syncthreads();
        __threadfence();

        // h2 = lrelu(agg2 + b2); x3 = h2 . W3   (warp per node)
        int n3 = g_cnt2;
        for (int i = bw; i < n3; i += 32) {
            int v = g_list2[i];
            float ya = lrelu(__ldcg(&g_agg2[(size_t)v * 64 + lane])      + __ldg(&b2[lane]));
            float yb = lrelu(__ldcg(&g_agg2[(size_t)v * 64 + lane + 32]) + __ldg(&b2[lane + 32]));
            float p = fmaf(ya, __ldg(&W3[lane]), yb * __ldg(&W3[lane + 32]));
            #pragma unroll
            for (int o = 16; o; o >>= 1) p += __shfl_down_sync(0xffffffffu, p, o);
            if (lane == 0) g_x3[v] = p;
        }
        __syncthreads();
        __threadfence();

        // final: sum x3[src] over node-1 in-edges
        __shared__ float red[32];
        int n1 = min(g_e1n, E1CAP);
        float s = 0.f;
        for (int i = threadIdx.x; i < n1; i += NTHR) s += __ldcg(&g_x3[g_e1s[i]]);
        #pragma unroll
        for (int o = 16; o; o >>= 1) s += __shfl_down_sync(0xffffffffu, s, o);
        if (lane == 0) red[threadIdx.x >> 5] = s;
        __syncthreads();
        if (threadIdx.x < 32) {
            float t = red[lane];
            #pragma unroll
            for (int o = 16; o; o >>= 1) t += __shfl_down_sync(0xffffffffu, t, o);
            if (lane == 0) out[0] = lrelu(t + __ldg(&b3[0]));
        }
    }
}

// ---------------------------------------------------------------------------
extern "C" void kernel_launch(void* const* d_in, const int* in_sizes, int n_in,
                              void* d_out, int out_size) {
    const float* in_feat = (const float*)d_in[0];
    const int*   src     = (const int*)  d_in[1];
    const int*   dst     = (const int*)  d_in[2];
    const float* W0 = (const float*)d_in[3];
    const float* b0 = (const float*)d_in[4];
    const float* W1 = (const float*)d_in[5];
    const float* b1 = (const float*)d_in[6];
    const float* W2 = (const float*)d_in[7];
    const float* b2 = (const float*)d_in[8];
    const float* W3 = (const float*)d_in[9];
    const float* b3 = (const float*)d_in[10];
    float* out = (float*)d_out;
    int E = in_sizes[1];

    gcn_persistent<<<NBLK, NTHR>>>(in_feat, src, dst, E,
                                   W0, b0, W1, b1, W2, b2, W3, b3, out);
}

// round 4
// speedup vs baseline: 2.7292x; 2.7292x over previous
#include <cuda_runtime.h>

// ---------------------------------------------------------------------------
// DummyGCN4: 4-layer GCN, output = h3[node 1] only.
// R4: multi-kernel backward-slice, 3 full edge scans.
//   scan1: agg0[d] += in_feat[s] for ALL edges (width-1 layer-0 aggregation,
//          no filtering needed) + capture node-1 in-edges (B2/list2/e1).
//   scan2: capture edges with dst in B2 (B1/list1/e2).
//   scan3: capture edges with dst in B1 (eb) — pure append, no bitmap build.
//   agg1:  agg1[d] += lrelu(agg0[s]*W0+b0) over eb (h0 fused, warp/edge).
//   h1x2:  per node in list1: h1 = lrelu(agg1@W1+b1); x2 = h1@W2 (warp/node).
//   tail:  single block: agg2 over e2, h2 = lrelu(agg2+b2), x3 = h2.W3,
//          final reduce over e1, out = lrelu(acc + b3).
// ---------------------------------------------------------------------------

#define MAXN 50048
#define BMW  1568
#define OUT_NODE 1
#define E1CAP  8192       // edges with dst == OUT_NODE   (expect ~16)
#define E2CAP  32768      // edges with dst in B2         (expect ~256)
#define EBCAP  262144     // edges with dst in B1         (expect ~4k)

__device__ unsigned g_B1[BMW], g_B2[BMW];
__device__ int   g_list1[MAXN], g_list2[MAXN];
__device__ int   g_cnt1, g_cnt2;
__device__ int   g_e1s[E1CAP];                 __device__ int g_e1n;
__device__ int   g_e2s[E2CAP],  g_e2d[E2CAP];  __device__ int g_e2n;
__device__ int   g_ebs[EBCAP],  g_ebd[EBCAP];  __device__ int g_ebn;
__device__ float g_agg0[MAXN];
__device__ float g_agg1[(size_t)MAXN * 64];
__device__ float g_x2[(size_t)MAXN * 64];
__device__ float g_agg2[(size_t)MAXN * 64];
__device__ float g_x3[MAXN];

__device__ __forceinline__ float lrelu(float x) { return x >= 0.f ? x : 0.01f * x; }
__device__ __forceinline__ bool tb(const unsigned* b, int i) {
    return (b[i >> 5] >> (i & 31)) & 1u;
}
__device__ __forceinline__ void zero64(float* a) {
    float4 z = make_float4(0.f, 0.f, 0.f, 0.f);
    float4* a4 = (float4*)a;
    #pragma unroll
    for (int j = 0; j < 16; j++) a4[j] = z;
}

// ---------------- k_clear: agg0 + bitmaps + counters ----------------
__global__ void k_clear() {
    int t = blockIdx.x * blockDim.x + threadIdx.x;
    if (t < MAXN) g_agg0[t] = 0.f;
    if (t < BMW) { g_B1[t] = 0; g_B2[t] = 0; }
    if (t == 0) { g_cnt1 = 0; g_cnt2 = 0; g_e1n = 0; g_e2n = 0; g_ebn = 0; }
}

// ---------------- scan1: agg0 for all edges + node-1 in-edge capture --------
__device__ __forceinline__ void hit32(int s) {
    int p = atomicAdd(&g_e1n, 1);
    if (p < E1CAP) g_e1s[p] = s;
    unsigned m = 1u << (s & 31);
    unsigned old = atomicOr(&g_B2[s >> 5], m);
    if (!(old & m)) {
        int q = atomicAdd(&g_cnt2, 1);
        g_list2[q] = s;
        zero64(&g_agg2[(size_t)s * 64]);
    }
}
__global__ void k_scan1(const int* __restrict__ src, const int* __restrict__ dst,
                        const float* __restrict__ in_feat, int E) {
    int t = blockIdx.x * blockDim.x + threadIdx.x;
    int base = t * 8;
    if (base + 7 < E) {
        int4 d4a = __ldg((const int4*)(dst + base));
        int4 d4b = __ldg((const int4*)(dst + base + 4));
        int4 s4a = __ldg((const int4*)(src + base));
        int4 s4b = __ldg((const int4*)(src + base + 4));
        int ss[8] = { s4a.x, s4a.y, s4a.z, s4a.w, s4b.x, s4b.y, s4b.z, s4b.w };
        int dd[8] = { d4a.x, d4a.y, d4a.z, d4a.w, d4b.x, d4b.y, d4b.z, d4b.w };
        float f[8];
        #pragma unroll
        for (int i = 0; i < 8; i++) f[i] = __ldg(&in_feat[ss[i]]);
        #pragma unroll
        for (int i = 0; i < 8; i++) atomicAdd(&g_agg0[dd[i]], f[i]);
        #pragma unroll
        for (int i = 0; i < 8; i++) if (dd[i] == OUT_NODE) hit32(ss[i]);
    } else {
        for (int e = base; e < E; e++) {
            int s = __ldg(&src[e]), d = __ldg(&dst[e]);
            atomicAdd(&g_agg0[d], __ldg(&in_feat[s]));
            if (d == OUT_NODE) hit32(s);
        }
    }
}

// ---------------- scan2: dst in B2 -> B1/list1/e2 ----------------
__device__ __forceinline__ void hit21(int s, int d) {
    int p = atomicAdd(&g_e2n, 1);
    if (p < E2CAP) { g_e2s[p] = s; g_e2d[p] = d; }
    unsigned m = 1u << (s & 31);
    unsigned old = atomicOr(&g_B1[s >> 5], m);
    if (!(old & m)) {
        int q = atomicAdd(&g_cnt1, 1);
        g_list1[q] = s;
        zero64(&g_agg1[(size_t)s * 64]);
    }
}
__global__ void k_scan2(const int* __restrict__ src, const int* __restrict__ dst, int E) {
    int t = blockIdx.x * blockDim.x + threadIdx.x;
    int base = t * 8;
    if (base + 7 < E) {
        int4 d4a = __ldg((const int4*)(dst + base));
        int4 d4b = __ldg((const int4*)(dst + base + 4));
        int dd[8] = { d4a.x, d4a.y, d4a.z, d4a.w, d4b.x, d4b.y, d4b.z, d4b.w };
        #pragma unroll
        for (int i = 0; i < 8; i++)
            if (tb(g_B2, dd[i])) hit21(__ldg(&src[base + i]), dd[i]);
    } else {
        for (int e = base; e < E; e++) {
            int d = __ldg(&dst[e]);
            if (tb(g_B2, d)) hit21(__ldg(&src[e]), d);
        }
    }
}

// ---------------- scan3: dst in B1 -> eb (pure capture) ----------------
__global__ void k_scan3(const int* __restrict__ src, const int* __restrict__ dst, int E) {
    int t = blockIdx.x * blockDim.x + threadIdx.x;
    int base = t * 8;
    if (base + 7 < E) {
        int4 d4a = __ldg((const int4*)(dst + base));
        int4 d4b = __ldg((const int4*)(dst + base + 4));
        int dd[8] = { d4a.x, d4a.y, d4a.z, d4a.w, d4b.x, d4b.y, d4b.z, d4b.w };
        #pragma unroll
        for (int i = 0; i < 8; i++) {
            if (tb(g_B1, dd[i])) {
                int p = atomicAdd(&g_ebn, 1);
                if (p < EBCAP) { g_ebs[p] = __ldg(&src[base + i]); g_ebd[p] = dd[i]; }
            }
        }
    } else {
        for (int e = base; e < E; e++) {
            int d = __ldg(&dst[e]);
            if (tb(g_B1, d)) {
                int p = atomicAdd(&g_ebn, 1);
                if (p < EBCAP) { g_ebs[p] = __ldg(&src[e]); g_ebd[p] = d; }
            }
        }
    }
}

// ---------------- agg1: agg1[d][:] += lrelu(agg0[s]*W0+b0), warp/edge -------
__global__ void k_agg1(const float* __restrict__ W0, const float* __restrict__ b0) {
    int n = min(g_ebn, EBCAP);
    int lane = threadIdx.x & 31;
    int warp = (blockIdx.x * blockDim.x + threadIdx.x) >> 5;
    int nw = (gridDim.x * blockDim.x) >> 5;
    float w0a = __ldg(&W0[lane]),      w0b = __ldg(&W0[lane + 32]);
    float b0a = __ldg(&b0[lane]),      b0b = __ldg(&b0[lane + 32]);
    for (int i = warp; i < n; i += nw) {
        int s = g_ebs[i], d = g_ebd[i];
        float a0 = g_agg0[s];
        float* a = &g_agg1[(size_t)d * 64];
        atomicAdd(&a[lane],      lrelu(fmaf(a0, w0a, b0a)));
        atomicAdd(&a[lane + 32], lrelu(fmaf(a0, w0b, b0b)));
    }
}

// ---------------- h1x2: per node v in list1 (warp/node) ----------------
__global__ void k_h1x2(const float* __restrict__ W1, const float* __restrict__ b1,
                       const float* __restrict__ W2) {
    int n = g_cnt1;
    int lane = threadIdx.x & 31;
    int warp = (blockIdx.x * blockDim.x + threadIdx.x) >> 5;
    int nw = (gridDim.x * blockDim.x) >> 5;
    for (int i = warp; i < n; i += nw) {
        int v = g_list1[i];
        float a0 = g_agg1[(size_t)v * 64 + lane];
        float a1 = g_agg1[(size_t)v * 64 + lane + 32];
        float h0r = __ldg(&b1[lane]);
        float h1r = __ldg(&b1[lane + 32]);
        float h2r = __ldg(&b1[lane + 64]);
        float h3r = __ldg(&b1[lane + 96]);
        #pragma unroll
        for (int k = 0; k < 64; k++) {
            float ak = __shfl_sync(0xffffffffu, (k < 32) ? a0 : a1, k & 31);
            const float* wr = &W1[k * 128];
            h0r = fmaf(ak, __ldg(&wr[lane]),      h0r);
            h1r = fmaf(ak, __ldg(&wr[lane + 32]), h1r);
            h2r = fmaf(ak, __ldg(&wr[lane + 64]), h2r);
            h3r = fmaf(ak, __ldg(&wr[lane + 96]), h3r);
        }
        float h[4] = { lrelu(h0r), lrelu(h1r), lrelu(h2r), lrelu(h3r) };
        float x0 = 0.f, x1 = 0.f;
        #pragma unroll
        for (int k = 0; k < 128; k++) {
            float hk = __shfl_sync(0xffffffffu, h[k >> 5], k & 31);
            const float* wr = &W2[k * 64];
            x0 = fmaf(hk, __ldg(&wr[lane]),      x0);
            x1 = fmaf(hk, __ldg(&wr[lane + 32]), x1);
        }
        g_x2[(size_t)v * 64 + lane]      = x0;
        g_x2[(size_t)v * 64 + lane + 32] = x1;
    }
}

// ---------------- tail: agg2 + h2x3 + final reduce + out (1 block) ----------
__global__ void __launch_bounds__(1024, 1)
k_tail(const float* __restrict__ b2, const float* __restrict__ W3,
       const float* __restrict__ b3, float* __restrict__ out) {
    int lane = threadIdx.x & 31;
    int bw = threadIdx.x >> 5;              // 0..31

    // agg2[d][:] += x2[s][:] over e2 (warp per edge)
    int n2 = min(g_e2n, E2CAP);
    for (int i = bw; i < n2; i += 32) {
        int s = g_e2s[i], d = g_e2d[i];
        float* a = &g_agg2[(size_t)d * 64];
        atomicAdd(&a[lane],      __ldcg(&g_x2[(size_t)s * 64 + lane]));
        atomicAdd(&a[lane + 32], __ldcg(&g_x2[(size_t)s * 64 + lane + 32]));
    }
    __syncthreads();

    // h2 = lrelu(agg2 + b2); x3 = h2 . W3 (warp per node)
    int n3 = g_cnt2;
    for (int i = bw; i < n3; i += 32) {
        int v = g_list2[i];
        float ya = lrelu(__ldcg(&g_agg2[(size_t)v * 64 + lane])      + __ldg(&b2[lane]));
        float yb = lrelu(__ldcg(&g_agg2[(size_t)v * 64 + lane + 32]) + __ldg(&b2[lane + 32]));
        float p = fmaf(ya, __ldg(&W3[lane]), yb * __ldg(&W3[lane + 32]));
        #pragma unroll
        for (int o = 16; o; o >>= 1) p += __shfl_down_sync(0xffffffffu, p, o);
        if (lane == 0) g_x3[v] = p;
    }
    __syncthreads();

    // final: sum x3[src] over node-1 in-edges
    __shared__ float red[32];
    int n1 = min(g_e1n, E1CAP);
    float s = 0.f;
    for (int i = threadIdx.x; i < n1; i += 1024) s += __ldcg(&g_x3[g_e1s[i]]);
    #pragma unroll
    for (int o = 16; o; o >>= 1) s += __shfl_down_sync(0xffffffffu, s, o);
    if (lane == 0) red[bw] = s;
    __syncthreads();
    if (threadIdx.x < 32) {
        float t = red[lane];
        #pragma unroll
        for (int o = 16; o; o >>= 1) t += __shfl_down_sync(0xffffffffu, t, o);
        if (lane == 0) out[0] = lrelu(t + __ldg(&b3[0]));
    }
}

// ---------------------------------------------------------------------------
extern "C" void kernel_launch(void* const* d_in, const int* in_sizes, int n_in,
                              void* d_out, int out_size) {
    const float* in_feat = (const float*)d_in[0];
    const int*   src     = (const int*)  d_in[1];
    const int*   dst     = (const int*)  d_in[2];
    const float* W0 = (const float*)d_in[3];
    const float* b0 = (const float*)d_in[4];
    const float* W1 = (const float*)d_in[5];
    const float* b1 = (const float*)d_in[6];
    const float* W2 = (const float*)d_in[7];
    const float* b2 = (const float*)d_in[8];
    const float* W3 = (const float*)d_in[9];
    const float* b3 = (const float*)d_in[10];
    float* out = (float*)d_out;

    int E = in_sizes[1];
    int T = (E + 7) / 8;                 // one thread per 8 edges
    int sb = (T + 255) / 256;

    k_clear<<<(MAXN + 255) / 256, 256>>>();
    k_scan1<<<sb, 256>>>(src, dst, in_feat, E);
    k_scan2<<<sb, 256>>>(src, dst, E);
    k_scan3<<<sb, 256>>>(src, dst, E);
    k_agg1<<<256, 256>>>(W0, b0);
    k_h1x2<<<128, 256>>>(W1, b1, W2);
    k_tail<<<1, 1024>>>(b2, W3, b3, out);
}